// round 9
// baseline (speedup 1.0000x reference)
#include <cuda_runtime.h>

#define BB     4
#define NN     8192
#define TPB    128
#define GSPLIT 16
#define CHUNK  (NN / GSPLIT)        // 512 gt points per block
#define QPT    8                    // query points per thread (4 packed pairs)
#define XT     (NN / (TPB * QPT))   // 8 query tiles
#define NWARP  (TPB / 32)

// dir0 partials: min_j(s+gg) per (b, chunk, query)  -> 2MB
__device__ float g_part0[BB * GSPLIT * NN];
// dir1 partials: min_i(d) per (b, query-tile, gt)   -> 1MB
__device__ float g_part1[BB * XT * NN];

typedef unsigned long long ull;

__device__ __forceinline__ ull fma2(ull a, ull b, ull c) {
    ull d;
    asm("fma.rn.f32x2 %0, %1, %2, %3;" : "=l"(d) : "l"(a), "l"(b), "l"(c));
    return d;
}
__device__ __forceinline__ ull add2(ull a, ull b) {
    ull d;
    asm("add.rn.f32x2 %0, %1, %2;" : "=l"(d) : "l"(a), "l"(b));
    return d;
}
// Pure bit-cast pack/unpack: register-pair aliasing, no MOVs.
__device__ __forceinline__ ull pack2(float lo, float hi) {
    return __double_as_longlong(
        __hiloint2double(__float_as_int(hi), __float_as_int(lo)));
}
__device__ __forceinline__ void unpack2(ull v, float& lo, float& hi) {
    const double d = __longlong_as_double(v);
    lo = __int_as_float(__double2loint(d));
    hi = __int_as_float(__double2hiint(d));
}

// Fused both-direction kernel. Per unique (query, gt) pair:
//   v0 = gg - 2 p.g   (3 FFMA2 chain)  -> dir0 row-min (pp added in reduce)
//   v1 = v0 + pp      (1 ADD2)         -> full sq dist -> dir1 col-min
// Col-min across the warp via REDUX.MIN.U32 on the float bits (valid order
// for non-negative floats; v1 >= -4e-7 from rounding, harmless at 1e-3 tol).
__global__ __launch_bounds__(TPB) void chamfer_fused_kernel(
    const float* __restrict__ pred, const float* __restrict__ gt,
    float* __restrict__ out) {
    // Duplicated gt layout for packed math (32B/point):
    //   sq[2j]   = {-2gx, -2gx, -2gy, -2gy}
    //   sq[2j+1] = {-2gz, -2gz, |g|^2, |g|^2}
    __shared__ float4 sq[2 * CHUNK];          // 16KB
    __shared__ float  colmin[NWARP * CHUNK];  // 8KB, per-warp dir1 col mins

    const int tid = threadIdx.x;
    const int wid = tid >> 5;
    const int b   = blockIdx.z;

    // Zero the scalar output once, before the reduce kernel's atomics.
    if (b == 0 && blockIdx.x == 0 && blockIdx.y == 0 && tid == 0)
        out[0] = 0.0f;

    const float* Pb = pred + (size_t)b * NN * 3;
    const float* Gb = gt   + (size_t)b * NN * 3;

    // --- cooperative load + transform + duplicate of gt chunk ---
    const int coff = blockIdx.y * CHUNK;
    for (int i = tid; i < CHUNK; i += TPB) {
        const float gx = Gb[(coff + i) * 3 + 0];
        const float gy = Gb[(coff + i) * 3 + 1];
        const float gz = Gb[(coff + i) * 3 + 2];
        const float gg = gx * gx + gy * gy + gz * gz;
        sq[2 * i]     = make_float4(-2.0f * gx, -2.0f * gx, -2.0f * gy, -2.0f * gy);
        sq[2 * i + 1] = make_float4(-2.0f * gz, -2.0f * gz, gg, gg);
    }
    __syncthreads();

    // --- each thread owns QPT=8 queries, as 4 packed f32x2 pairs ---
    const int base = (blockIdx.x * TPB + tid) * QPT;

    ull pxx[QPT / 2], pyy[QPT / 2], pzz[QPT / 2], pp01[QPT / 2];
#pragma unroll
    for (int p = 0; p < QPT / 2; p++) {
        const int   q0 = base + 2 * p, q1 = q0 + 1;
        const float ax = Pb[q0 * 3 + 0], ay = Pb[q0 * 3 + 1], az = Pb[q0 * 3 + 2];
        const float bx = Pb[q1 * 3 + 0], by = Pb[q1 * 3 + 1], bz = Pb[q1 * 3 + 2];
        pxx[p]  = pack2(ax, bx);
        pyy[p]  = pack2(ay, by);
        pzz[p]  = pack2(az, bz);
        pp01[p] = pack2(ax * ax + ay * ay + az * az,
                        bx * bx + by * by + bz * bz);
    }

    float mn[QPT];
#pragma unroll
    for (int q = 0; q < QPT; q++) mn[q] = 3.4e38f;

    const ulonglong2* __restrict__ s2 = reinterpret_cast<const ulonglong2*>(sq);
#pragma unroll 8
    for (int j = 0; j < CHUNK; j++) {
        const ulonglong2 a = s2[2 * j];        // {-2gx,-2gx, -2gy,-2gy}
        const ulonglong2 c = s2[2 * j + 1];    // {-2gz,-2gz,  gg,  gg }
        float t[QPT];
#pragma unroll
        for (int p = 0; p < QPT / 2; p++) {
            const ull s = fma2(pxx[p], a.x, fma2(pyy[p], a.y, fma2(pzz[p], c.x, c.y)));
            float lo, hi;
            unpack2(s, lo, hi);
            mn[2 * p]     = fminf(mn[2 * p], lo);       // dir0 row-min (v0)
            mn[2 * p + 1] = fminf(mn[2 * p + 1], hi);
            const ull v = add2(s, pp01[p]);             // full distance (v1)
            unpack2(v, t[2 * p], t[2 * p + 1]);
        }
        // dir1: min over this thread's 8 queries (in-thread tree)...
        const float m = fminf(fminf(fminf(t[0], t[1]), fminf(t[2], t[3])),
                              fminf(fminf(t[4], t[5]), fminf(t[6], t[7])));
        // ...then across the 32 lanes in ONE instruction (u32 order == f32
        // order for non-negative values).
        const unsigned r = __reduce_min_sync(0xffffffffu,
                                             __float_as_uint(m));
        colmin[wid * CHUNK + j] = __uint_as_float(r);  // all lanes same val
    }

    // dir0 partials out (min of v0 = s+gg; pp added in the reduce kernel)
    const size_t o0 = ((size_t)(b * GSPLIT + blockIdx.y)) * NN + base;
#pragma unroll
    for (int q = 0; q < QPT; q++) g_part0[o0 + q] = mn[q];

    __syncthreads();

    // dir1: combine the NWARP per-warp col-mins, write per-(b, query-tile) slice
    for (int j = tid; j < CHUNK; j += TPB) {
        float m = colmin[j];
#pragma unroll
        for (int w = 1; w < NWARP; w++) m = fminf(m, colmin[w * CHUNK + j]);
        g_part1[((size_t)(b * XT + blockIdx.x)) * NN + coff + j] = m;
    }
}

// Final reduce: dir0 = min over chunks + ||p||^2 ; dir1 = min over query tiles.
// result = sum(all dists) / (B*N)   (N == M, forward_weight = 1)
#define TPB_RED 256
__global__ __launch_bounds__(TPB_RED) void chamfer_reduce_kernel(
    const float* __restrict__ pred, float* __restrict__ out) {
    __shared__ float red[TPB_RED];

    const int tid  = threadIdx.x;
    const int gidx = blockIdx.x * TPB_RED + tid;     // 0 .. 2*B*N-1

    float val;
    if (gidx < BB * NN) {                        // dir0 (pred -> gt)
        const int b = gidx / NN, q = gidx % NN;
        const float* Pb = pred + (size_t)b * NN * 3;
        const float px = Pb[q * 3 + 0];
        const float py = Pb[q * 3 + 1];
        const float pz = Pb[q * 3 + 2];
        float m = 3.4e38f;
#pragma unroll
        for (int c = 0; c < GSPLIT; c++)
            m = fminf(m, g_part0[((size_t)(b * GSPLIT + c)) * NN + q]);
        val = m + (px * px + py * py + pz * pz);
    } else {                                     // dir1 (gt -> pred)
        const int r = gidx - BB * NN;
        const int b = r / NN, j = r % NN;
        float m = 3.4e38f;
#pragma unroll
        for (int x = 0; x < XT; x++)
            m = fminf(m, g_part1[((size_t)(b * XT + x)) * NN + j]);
        val = m;
    }

    red[tid] = val;
    __syncthreads();
#pragma unroll
    for (int s = TPB_RED / 2; s > 0; s >>= 1) {
        if (tid < s) red[tid] += red[tid + s];
        __syncthreads();
    }
    if (tid == 0)
        atomicAdd(out, red[0] * (1.0f / ((float)BB * (float)NN)));
}

extern "C" void kernel_launch(void* const* d_in, const int* in_sizes, int n_in,
                              void* d_out, int out_size) {
    const float* pred = (const float*)d_in[0];
    const float* gt   = (const float*)d_in[1];
    float*       out  = (float*)d_out;

    dim3 grid(XT, GSPLIT, BB);   // 8 x 16 x 4 = 512 blocks, single launch
    chamfer_fused_kernel<<<grid, TPB>>>(pred, gt, out);

    chamfer_reduce_kernel<<<(2 * BB * NN) / TPB_RED, TPB_RED>>>(pred, out);
}

// round 10
// speedup vs baseline: 1.5240x; 1.5240x over previous
#include <cuda_runtime.h>

#define BB     4
#define NN     8192
#define TPB    128
#define GSPLIT 32
#define CHUNK  (NN / GSPLIT)        // 256 gt points per block
#define QPT    8                    // query points per thread (4 packed pairs)
#define XT     (NN / (TPB * QPT))   // 8 query tiles
#define NWARP  (TPB / 32)

// dir0 partials: min_j(s+gg) per (b, chunk, query)  -> 4MB
__device__ float g_part0[BB * GSPLIT * NN];
// dir1 partials: min_i(d) per (b, query-tile, gt)   -> 1MB
__device__ float g_part1[BB * XT * NN];

typedef unsigned long long ull;

__device__ __forceinline__ ull fma2(ull a, ull b, ull c) {
    ull d;
    asm("fma.rn.f32x2 %0, %1, %2, %3;" : "=l"(d) : "l"(a), "l"(b), "l"(c));
    return d;
}
__device__ __forceinline__ ull add2(ull a, ull b) {
    ull d;
    asm("add.rn.f32x2 %0, %1, %2;" : "=l"(d) : "l"(a), "l"(b));
    return d;
}
// Pure bit-cast pack/unpack: register-pair aliasing, no MOVs.
__device__ __forceinline__ ull pack2(float lo, float hi) {
    return __double_as_longlong(
        __hiloint2double(__float_as_int(hi), __float_as_int(lo)));
}
__device__ __forceinline__ void unpack2(ull v, float& lo, float& hi) {
    const double d = __longlong_as_double(v);
    lo = __int_as_float(__double2loint(d));
    hi = __int_as_float(__double2hiint(d));
}

// Fused both-direction kernel. Per unique (query, gt) pair:
//   v0 = gg - 2 p.g   (3 FFMA2 chain)  -> dir0 row-min (pp added in reduce)
//   v1 = v0 + pp      (1 ADD2)         -> full sq dist -> dir1 col-min
// Col-min across the warp via SHFL butterfly (R9 proved REDUX.MIN in the hot
// loop serializes on MIO; butterflies pipeline).
__global__ __launch_bounds__(TPB) void chamfer_fused_kernel(
    const float* __restrict__ pred, const float* __restrict__ gt,
    float* __restrict__ out) {
    // Duplicated gt layout for packed math (32B/point):
    //   sq[2j]   = {-2gx, -2gx, -2gy, -2gy}
    //   sq[2j+1] = {-2gz, -2gz, |g|^2, |g|^2}
    __shared__ float4 sq[2 * CHUNK];          // 8KB
    __shared__ float  colmin[NWARP * CHUNK];  // 4KB, per-warp dir1 col mins

    const int tid = threadIdx.x;
    const int wid = tid >> 5;
    const int b   = blockIdx.z;

    // Zero the scalar output once, before the reduce kernel's atomics.
    if (b == 0 && blockIdx.x == 0 && blockIdx.y == 0 && tid == 0)
        out[0] = 0.0f;

    const float* Pb = pred + (size_t)b * NN * 3;
    const float* Gb = gt   + (size_t)b * NN * 3;

    // --- cooperative load + transform + duplicate of gt chunk ---
    const int coff = blockIdx.y * CHUNK;
    for (int i = tid; i < CHUNK; i += TPB) {
        const float gx = Gb[(coff + i) * 3 + 0];
        const float gy = Gb[(coff + i) * 3 + 1];
        const float gz = Gb[(coff + i) * 3 + 2];
        const float gg = gx * gx + gy * gy + gz * gz;
        sq[2 * i]     = make_float4(-2.0f * gx, -2.0f * gx, -2.0f * gy, -2.0f * gy);
        sq[2 * i + 1] = make_float4(-2.0f * gz, -2.0f * gz, gg, gg);
    }
    __syncthreads();

    // --- each thread owns QPT=8 queries, as 4 packed f32x2 pairs ---
    const int base = (blockIdx.x * TPB + tid) * QPT;

    ull pxx[QPT / 2], pyy[QPT / 2], pzz[QPT / 2], pp01[QPT / 2];
#pragma unroll
    for (int p = 0; p < QPT / 2; p++) {
        const int   q0 = base + 2 * p, q1 = q0 + 1;
        const float ax = Pb[q0 * 3 + 0], ay = Pb[q0 * 3 + 1], az = Pb[q0 * 3 + 2];
        const float bx = Pb[q1 * 3 + 0], by = Pb[q1 * 3 + 1], bz = Pb[q1 * 3 + 2];
        pxx[p]  = pack2(ax, bx);
        pyy[p]  = pack2(ay, by);
        pzz[p]  = pack2(az, bz);
        pp01[p] = pack2(ax * ax + ay * ay + az * az,
                        bx * bx + by * by + bz * bz);
    }

    float mn[QPT];
#pragma unroll
    for (int q = 0; q < QPT; q++) mn[q] = 3.4e38f;

    const ulonglong2* __restrict__ s2 = reinterpret_cast<const ulonglong2*>(sq);
#pragma unroll 4
    for (int j = 0; j < CHUNK; j++) {
        const ulonglong2 a = s2[2 * j];        // {-2gx,-2gx, -2gy,-2gy}
        const ulonglong2 c = s2[2 * j + 1];    // {-2gz,-2gz,  gg,  gg }
        float t[QPT];
#pragma unroll
        for (int p = 0; p < QPT / 2; p++) {
            const ull s = fma2(pxx[p], a.x, fma2(pyy[p], a.y, fma2(pzz[p], c.x, c.y)));
            float lo, hi;
            unpack2(s, lo, hi);
            mn[2 * p]     = fminf(mn[2 * p], lo);       // dir0 row-min (v0)
            mn[2 * p + 1] = fminf(mn[2 * p + 1], hi);
            const ull v = add2(s, pp01[p]);             // full distance (v1)
            unpack2(v, t[2 * p], t[2 * p + 1]);
        }
        // dir1: min over this thread's 8 queries...
        float m = fminf(fminf(fminf(t[0], t[1]), fminf(t[2], t[3])),
                        fminf(fminf(t[4], t[5]), fminf(t[6], t[7])));
        // ...then across the warp's 32 lanes (256 queries total)
        m = fminf(m, __shfl_xor_sync(0xffffffffu, m, 16));
        m = fminf(m, __shfl_xor_sync(0xffffffffu, m, 8));
        m = fminf(m, __shfl_xor_sync(0xffffffffu, m, 4));
        m = fminf(m, __shfl_xor_sync(0xffffffffu, m, 2));
        m = fminf(m, __shfl_xor_sync(0xffffffffu, m, 1));
        colmin[wid * CHUNK + j] = m;   // all lanes same value/addr: one write wins
    }

    // dir0 partials out (min of v0 = s+gg; pp added in the reduce kernel)
    const size_t o0 = ((size_t)(b * GSPLIT + blockIdx.y)) * NN + base;
#pragma unroll
    for (int q = 0; q < QPT; q++) g_part0[o0 + q] = mn[q];

    __syncthreads();

    // dir1: combine the NWARP per-warp col-mins, write per-(b, query-tile) slice
    for (int j = tid; j < CHUNK; j += TPB) {
        float m = colmin[j];
#pragma unroll
        for (int w = 1; w < NWARP; w++) m = fminf(m, colmin[w * CHUNK + j]);
        g_part1[((size_t)(b * XT + blockIdx.x)) * NN + coff + j] = m;
    }
}

// Final reduce: dir0 = min over chunks + ||p||^2 ; dir1 = min over query tiles.
// result = sum(all dists) / (B*N)   (N == M, forward_weight = 1)
#define TPB_RED 256
__global__ __launch_bounds__(TPB_RED) void chamfer_reduce_kernel(
    const float* __restrict__ pred, float* __restrict__ out) {
    __shared__ float red[TPB_RED];

    const int tid  = threadIdx.x;
    const int gidx = blockIdx.x * TPB_RED + tid;     // 0 .. 2*B*N-1

    float val;
    if (gidx < BB * NN) {                        // dir0 (pred -> gt)
        const int b = gidx / NN, q = gidx % NN;
        const float* Pb = pred + (size_t)b * NN * 3;
        const float px = Pb[q * 3 + 0];
        const float py = Pb[q * 3 + 1];
        const float pz = Pb[q * 3 + 2];
        float m = 3.4e38f;
#pragma unroll
        for (int c = 0; c < GSPLIT; c++)
            m = fminf(m, g_part0[((size_t)(b * GSPLIT + c)) * NN + q]);
        val = m + (px * px + py * py + pz * pz);
    } else {                                     // dir1 (gt -> pred)
        const int r = gidx - BB * NN;
        const int b = r / NN, j = r % NN;
        float m = 3.4e38f;
#pragma unroll
        for (int x = 0; x < XT; x++)
            m = fminf(m, g_part1[((size_t)(b * XT + x)) * NN + j]);
        val = m;
    }

    red[tid] = val;
    __syncthreads();
#pragma unroll
    for (int s = TPB_RED / 2; s > 0; s >>= 1) {
        if (tid < s) red[tid] += red[tid + s];
        __syncthreads();
    }
    if (tid == 0)
        atomicAdd(out, red[0] * (1.0f / ((float)BB * (float)NN)));
}

extern "C" void kernel_launch(void* const* d_in, const int* in_sizes, int n_in,
                              void* d_out, int out_size) {
    const float* pred = (const float*)d_in[0];
    const float* gt   = (const float*)d_in[1];
    float*       out  = (float*)d_out;

    dim3 grid(XT, GSPLIT, BB);   // 8 x 32 x 4 = 1024 blocks, single launch
    chamfer_fused_kernel<<<grid, TPB>>>(pred, gt, out);

    chamfer_reduce_kernel<<<(2 * BB * NN) / TPB_RED, TPB_RED>>>(pred, out);
}

// round 11
// speedup vs baseline: 1.5950x; 1.0466x over previous
#include <cuda_runtime.h>

#define BB     4
#define NN     8192
#define TPB    128
#define GSPLIT 32
#define CHUNK  (NN / GSPLIT)        // 256 gt points per block
#define QPT    8                    // query points per thread (4 packed pairs)
#define XT     (NN / (TPB * QPT))   // 8 query tiles
#define NWARP  (TPB / 32)
#define JT     4                    // columns per iteration (butterfly ILP)

// dir0 partials: min_j(s+gg) per (b, chunk, query)  -> 4MB
__device__ float g_part0[BB * GSPLIT * NN];
// dir1 partials: min_i(d) per (b, query-tile, gt)   -> 1MB
__device__ float g_part1[BB * XT * NN];

typedef unsigned long long ull;

__device__ __forceinline__ ull fma2(ull a, ull b, ull c) {
    ull d;
    asm("fma.rn.f32x2 %0, %1, %2, %3;" : "=l"(d) : "l"(a), "l"(b), "l"(c));
    return d;
}
__device__ __forceinline__ ull add2(ull a, ull b) {
    ull d;
    asm("add.rn.f32x2 %0, %1, %2;" : "=l"(d) : "l"(a), "l"(b));
    return d;
}
// Pure bit-cast pack/unpack: register-pair aliasing, no MOVs.
__device__ __forceinline__ ull pack2(float lo, float hi) {
    return __double_as_longlong(
        __hiloint2double(__float_as_int(hi), __float_as_int(lo)));
}
__device__ __forceinline__ void unpack2(ull v, float& lo, float& hi) {
    const double d = __longlong_as_double(v);
    lo = __int_as_float(__double2loint(d));
    hi = __int_as_float(__double2hiint(d));
}

// Fused both-direction kernel. Per unique (query, gt) pair:
//   v0 = gg - 2 p.g   (3 FFMA2 chain)  -> dir0 row-min (pp added in reduce)
//   v1 = v0 + pp      (1 ADD2)         -> full sq dist -> dir1 col-min
// dir1 col-min across lanes: 4 butterflies run interleaved (JT=4 columns per
// iteration) so the 5-stage SHFL chains overlap instead of serializing.
__global__ __launch_bounds__(TPB, 7) void chamfer_fused_kernel(
    const float* __restrict__ pred, const float* __restrict__ gt,
    float* __restrict__ out) {
    // Duplicated gt layout for packed math (32B/point):
    //   sq[2j]   = {-2gx, -2gx, -2gy, -2gy}
    //   sq[2j+1] = {-2gz, -2gz, |g|^2, |g|^2}
    __shared__ float4 sq[2 * CHUNK];          // 8KB
    __shared__ float  colmin[NWARP * CHUNK];  // 4KB, per-warp dir1 col mins

    const int tid = threadIdx.x;
    const int wid = tid >> 5;
    const int b   = blockIdx.z;

    // Zero the scalar output once, before the reduce kernel's atomics.
    if (b == 0 && blockIdx.x == 0 && blockIdx.y == 0 && tid == 0)
        out[0] = 0.0f;

    const float* Pb = pred + (size_t)b * NN * 3;
    const float* Gb = gt   + (size_t)b * NN * 3;

    // --- cooperative load + transform + duplicate of gt chunk ---
    const int coff = blockIdx.y * CHUNK;
    for (int i = tid; i < CHUNK; i += TPB) {
        const float gx = Gb[(coff + i) * 3 + 0];
        const float gy = Gb[(coff + i) * 3 + 1];
        const float gz = Gb[(coff + i) * 3 + 2];
        const float gg = gx * gx + gy * gy + gz * gz;
        sq[2 * i]     = make_float4(-2.0f * gx, -2.0f * gx, -2.0f * gy, -2.0f * gy);
        sq[2 * i + 1] = make_float4(-2.0f * gz, -2.0f * gz, gg, gg);
    }
    __syncthreads();

    // --- each thread owns QPT=8 queries, as 4 packed f32x2 pairs ---
    const int base = (blockIdx.x * TPB + tid) * QPT;

    ull pxx[QPT / 2], pyy[QPT / 2], pzz[QPT / 2], pp01[QPT / 2];
#pragma unroll
    for (int p = 0; p < QPT / 2; p++) {
        const int   q0 = base + 2 * p, q1 = q0 + 1;
        const float ax = Pb[q0 * 3 + 0], ay = Pb[q0 * 3 + 1], az = Pb[q0 * 3 + 2];
        const float bx = Pb[q1 * 3 + 0], by = Pb[q1 * 3 + 1], bz = Pb[q1 * 3 + 2];
        pxx[p]  = pack2(ax, bx);
        pyy[p]  = pack2(ay, by);
        pzz[p]  = pack2(az, bz);
        pp01[p] = pack2(ax * ax + ay * ay + az * az,
                        bx * bx + by * by + bz * bz);
    }

    float mn[QPT];
#pragma unroll
    for (int q = 0; q < QPT; q++) mn[q] = 3.4e38f;

    const ulonglong2* __restrict__ s2 = reinterpret_cast<const ulonglong2*>(sq);

    for (int j0 = 0; j0 < CHUNK; j0 += JT) {
        float m4[JT];
        // --- compute phase: JT columns, registers reused per column ---
#pragma unroll
        for (int c = 0; c < JT; c++) {
            const int        j = j0 + c;
            const ulonglong2 a = s2[2 * j];       // {-2gx,-2gx, -2gy,-2gy}
            const ulonglong2 w = s2[2 * j + 1];   // {-2gz,-2gz,  gg,  gg }
            float t[QPT];
#pragma unroll
            for (int p = 0; p < QPT / 2; p++) {
                const ull s = fma2(pxx[p], a.x,
                                   fma2(pyy[p], a.y, fma2(pzz[p], w.x, w.y)));
                float lo, hi;
                unpack2(s, lo, hi);
                mn[2 * p]     = fminf(mn[2 * p], lo);   // dir0 row-min (v0)
                mn[2 * p + 1] = fminf(mn[2 * p + 1], hi);
                const ull v = add2(s, pp01[p]);         // full distance (v1)
                unpack2(v, t[2 * p], t[2 * p + 1]);
            }
            m4[c] = fminf(fminf(fminf(t[0], t[1]), fminf(t[2], t[3])),
                          fminf(fminf(t[4], t[5]), fminf(t[6], t[7])));
        }
        // --- 4 interleaved butterflies (independent chains overlap) ---
#pragma unroll
        for (int st = 16; st >= 1; st >>= 1) {
#pragma unroll
            for (int c = 0; c < JT; c++)
                m4[c] = fminf(m4[c], __shfl_xor_sync(0xffffffffu, m4[c], st));
        }
        // one same-address STS.128 (all lanes hold identical values)
        *reinterpret_cast<float4*>(&colmin[wid * CHUNK + j0]) =
            make_float4(m4[0], m4[1], m4[2], m4[3]);
    }

    // dir0 partials out (min of v0 = s+gg; pp added in the reduce kernel)
    const size_t o0 = ((size_t)(b * GSPLIT + blockIdx.y)) * NN + base;
#pragma unroll
    for (int q = 0; q < QPT; q++) g_part0[o0 + q] = mn[q];

    __syncthreads();

    // dir1: combine the NWARP per-warp col-mins, write per-(b, query-tile) slice
    for (int j = tid; j < CHUNK; j += TPB) {
        float m = colmin[j];
#pragma unroll
        for (int w = 1; w < NWARP; w++) m = fminf(m, colmin[w * CHUNK + j]);
        g_part1[((size_t)(b * XT + blockIdx.x)) * NN + coff + j] = m;
    }
}

// Final reduce: dir0 = min over chunks + ||p||^2 ; dir1 = min over query tiles.
// result = sum(all dists) / (B*N)   (N == M, forward_weight = 1)
#define TPB_RED 256
__global__ __launch_bounds__(TPB_RED) void chamfer_reduce_kernel(
    const float* __restrict__ pred, float* __restrict__ out) {
    __shared__ float red[TPB_RED];

    const int tid  = threadIdx.x;
    const int gidx = blockIdx.x * TPB_RED + tid;     // 0 .. 2*B*N-1

    float val;
    if (gidx < BB * NN) {                        // dir0 (pred -> gt)
        const int b = gidx / NN, q = gidx % NN;
        const float* Pb = pred + (size_t)b * NN * 3;
        const float px = Pb[q * 3 + 0];
        const float py = Pb[q * 3 + 1];
        const float pz = Pb[q * 3 + 2];
        float m = 3.4e38f;
#pragma unroll
        for (int c = 0; c < GSPLIT; c++)
            m = fminf(m, g_part0[((size_t)(b * GSPLIT + c)) * NN + q]);
        val = m + (px * px + py * py + pz * pz);
    } else {                                     // dir1 (gt -> pred)
        const int r = gidx - BB * NN;
        const int b = r / NN, j = r % NN;
        float m = 3.4e38f;
#pragma unroll
        for (int x = 0; x < XT; x++)
            m = fminf(m, g_part1[((size_t)(b * XT + x)) * NN + j]);
        val = m;
    }

    red[tid] = val;
    __syncthreads();
#pragma unroll
    for (int s = TPB_RED / 2; s > 0; s >>= 1) {
        if (tid < s) red[tid] += red[tid + s];
        __syncthreads();
    }
    if (tid == 0)
        atomicAdd(out, red[0] * (1.0f / ((float)BB * (float)NN)));
}

extern "C" void kernel_launch(void* const* d_in, const int* in_sizes, int n_in,
                              void* d_out, int out_size) {
    const float* pred = (const float*)d_in[0];
    const float* gt   = (const float*)d_in[1];
    float*       out  = (float*)d_out;

    dim3 grid(XT, GSPLIT, BB);   // 8 x 32 x 4 = 1024 blocks, single launch
    chamfer_fused_kernel<<<grid, TPB>>>(pred, gt, out);

    chamfer_reduce_kernel<<<(2 * BB * NN) / TPB_RED, TPB_RED>>>(pred, out);
}

// round 13
// speedup vs baseline: 1.7402x; 1.0910x over previous
#include <cuda_runtime.h>

#define BB     4
#define NN     8192
#define TPB    128
#define GSPLIT 32
#define CHUNK  (NN / GSPLIT)        // 256 gt points per block
#define QPT    8                    // query points per thread (4 packed pairs)
#define XT     (NN / (TPB * QPT))   // 8 query tiles
#define NWARP  (TPB / 32)
#define JT     4                    // columns per iteration (butterfly ILP)
#define NCLS   4                    // lane classes kept after truncated butterfly

// dir0 partials: min_j(s+gg) per (b, chunk, query)  -> 4MB
__device__ float g_part0[BB * GSPLIT * NN];
// dir1 partials: min_i(d) per (b, query-tile, gt)   -> 1MB
__device__ float g_part1[BB * XT * NN];

typedef unsigned long long ull;

__device__ __forceinline__ ull fma2(ull a, ull b, ull c) {
    ull d;
    asm("fma.rn.f32x2 %0, %1, %2, %3;" : "=l"(d) : "l"(a), "l"(b), "l"(c));
    return d;
}
__device__ __forceinline__ ull add2(ull a, ull b) {
    ull d;
    asm("add.rn.f32x2 %0, %1, %2;" : "=l"(d) : "l"(a), "l"(b));
    return d;
}
// Pure bit-cast pack/unpack: register-pair aliasing, no MOVs.
__device__ __forceinline__ ull pack2(float lo, float hi) {
    return __double_as_longlong(
        __hiloint2double(__float_as_int(hi), __float_as_int(lo)));
}
__device__ __forceinline__ void unpack2(ull v, float& lo, float& hi) {
    const double d = __longlong_as_double(v);
    lo = __int_as_float(__double2loint(d));
    hi = __int_as_float(__double2hiint(d));
}

// Fused both-direction kernel. Per unique (query, gt) pair:
//   v0 = gg - 2 p.g   (3 FFMA2 chain)  -> dir0 row-min (pp added in reduce)
//   v1 = v0 + pp      (1 ADD2)         -> full sq dist -> dir1 col-min
// dir1 col-min: truncated 3-stage butterfly (xor 16,8,4) leaves 4 lane-class
// partial mins; lanes 0-3 store them, the block epilogue finishes. This cuts
// the per-column SHFL count 5->3 (SHFL shares the MIO pipe with LDS — the
// R9 REDUX regression and R11's muted ILP gain both point at MIO occupancy).
__global__ __launch_bounds__(TPB, 7) void chamfer_fused_kernel(
    const float* __restrict__ pred, const float* __restrict__ gt,
    float* __restrict__ out) {
    // Duplicated gt layout for packed math (32B/point):
    //   sq[2j]   = {-2gx, -2gx, -2gy, -2gy}
    //   sq[2j+1] = {-2gz, -2gz, |g|^2, |g|^2}
    __shared__ float4 sq[2 * CHUNK];                  // 8KB
    __shared__ float  colmin[NWARP][NCLS][CHUNK];     // 16KB

    const int tid  = threadIdx.x;
    const int wid  = tid >> 5;
    const int lane = tid & 31;
    const int b    = blockIdx.z;

    // Zero the scalar output once, before the reduce kernel's atomics.
    if (b == 0 && blockIdx.x == 0 && blockIdx.y == 0 && tid == 0)
        out[0] = 0.0f;

    const float* Pb = pred + (size_t)b * NN * 3;
    const float* Gb = gt   + (size_t)b * NN * 3;

    // --- cooperative load + transform + duplicate of gt chunk ---
    const int coff = blockIdx.y * CHUNK;
    for (int i = tid; i < CHUNK; i += TPB) {
        const float gx = Gb[(coff + i) * 3 + 0];
        const float gy = Gb[(coff + i) * 3 + 1];
        const float gz = Gb[(coff + i) * 3 + 2];
        const float gg = gx * gx + gy * gy + gz * gz;
        sq[2 * i]     = make_float4(-2.0f * gx, -2.0f * gx, -2.0f * gy, -2.0f * gy);
        sq[2 * i + 1] = make_float4(-2.0f * gz, -2.0f * gz, gg, gg);
    }
    __syncthreads();

    // --- each thread owns QPT=8 queries, as 4 packed f32x2 pairs ---
    const int base = (blockIdx.x * TPB + tid) * QPT;

    ull pxx[QPT / 2], pyy[QPT / 2], pzz[QPT / 2], pp01[QPT / 2];
#pragma unroll
    for (int p = 0; p < QPT / 2; p++) {
        const int   q0 = base + 2 * p, q1 = q0 + 1;
        const float ax = Pb[q0 * 3 + 0], ay = Pb[q0 * 3 + 1], az = Pb[q0 * 3 + 2];
        const float bx = Pb[q1 * 3 + 0], by = Pb[q1 * 3 + 1], bz = Pb[q1 * 3 + 2];
        pxx[p]  = pack2(ax, bx);
        pyy[p]  = pack2(ay, by);
        pzz[p]  = pack2(az, bz);
        pp01[p] = pack2(ax * ax + ay * ay + az * az,
                        bx * bx + by * by + bz * bz);
    }

    float mn[QPT];
#pragma unroll
    for (int q = 0; q < QPT; q++) mn[q] = 3.4e38f;

    const ulonglong2* __restrict__ s2 = reinterpret_cast<const ulonglong2*>(sq);

    for (int j0 = 0; j0 < CHUNK; j0 += JT) {
        float m4[JT];
        // --- compute phase: JT columns, registers reused per column ---
#pragma unroll
        for (int c = 0; c < JT; c++) {
            const int        j = j0 + c;
            const ulonglong2 a = s2[2 * j];       // {-2gx,-2gx, -2gy,-2gy}
            const ulonglong2 w = s2[2 * j + 1];   // {-2gz,-2gz,  gg,  gg }
            float t[QPT];
#pragma unroll
            for (int p = 0; p < QPT / 2; p++) {
                const ull s = fma2(pxx[p], a.x,
                                   fma2(pyy[p], a.y, fma2(pzz[p], w.x, w.y)));
                float lo, hi;
                unpack2(s, lo, hi);
                mn[2 * p]     = fminf(mn[2 * p], lo);   // dir0 row-min (v0)
                mn[2 * p + 1] = fminf(mn[2 * p + 1], hi);
                const ull v = add2(s, pp01[p]);         // full distance (v1)
                unpack2(v, t[2 * p], t[2 * p + 1]);
            }
            m4[c] = fminf(fminf(fminf(t[0], t[1]), fminf(t[2], t[3])),
                          fminf(fminf(t[4], t[5]), fminf(t[6], t[7])));
        }
        // --- truncated butterfly: 3 interleaved stages (xor 16, 8, 4) ---
        // After this every lane holds the min of its 8-lane class (lane&3).
#pragma unroll
        for (int st = 16; st >= 4; st >>= 1) {
#pragma unroll
            for (int c = 0; c < JT; c++)
                m4[c] = fminf(m4[c], __shfl_xor_sync(0xffffffffu, m4[c], st));
        }
        // lanes 0-3 each store their class row for these 4 columns (STS.128)
        if (lane < NCLS)
            *reinterpret_cast<float4*>(&colmin[wid][lane][j0]) =
                make_float4(m4[0], m4[1], m4[2], m4[3]);
    }

    // dir0 partials out (min of v0 = s+gg; pp added in the reduce kernel)
    const size_t o0 = ((size_t)(b * GSPLIT + blockIdx.y)) * NN + base;
#pragma unroll
    for (int q = 0; q < QPT; q++) g_part0[o0 + q] = mn[q];

    __syncthreads();

    // dir1 epilogue: combine NWARP x NCLS partial mins per column
    for (int j = tid; j < CHUNK; j += TPB) {
        float m = colmin[0][0][j];
#pragma unroll
        for (int w = 0; w < NWARP; w++)
#pragma unroll
            for (int c = 0; c < NCLS; c++)
                m = fminf(m, colmin[w][c][j]);
        g_part1[((size_t)(b * XT + blockIdx.x)) * NN + coff + j] = m;
    }
}

// Final reduce: dir0 = min over chunks + ||p||^2 ; dir1 = min over query tiles.
// result = sum(all dists) / (B*N)   (N == M, forward_weight = 1)
#define TPB_RED 256
__global__ __launch_bounds__(TPB_RED) void chamfer_reduce_kernel(
    const float* __restrict__ pred, float* __restrict__ out) {
    __shared__ float red[TPB_RED];

    const int tid  = threadIdx.x;
    const int gidx = blockIdx.x * TPB_RED + tid;     // 0 .. 2*B*N-1

    float val;
    if (gidx < BB * NN) {                        // dir0 (pred -> gt)
        const int b = gidx / NN, q = gidx % NN;
        const float* Pb = pred + (size_t)b * NN * 3;
        const float px = Pb[q * 3 + 0];
        const float py = Pb[q * 3 + 1];
        const float pz = Pb[q * 3 + 2];
        float m = 3.4e38f;
#pragma unroll
        for (int c = 0; c < GSPLIT; c++)
            m = fminf(m, g_part0[((size_t)(b * GSPLIT + c)) * NN + q]);
        val = m + (px * px + py * py + pz * pz);
    } else {                                     // dir1 (gt -> pred)
        const int r = gidx - BB * NN;
        const int b = r / NN, j = r % NN;
        float m = 3.4e38f;
#pragma unroll
        for (int x = 0; x < XT; x++)
            m = fminf(m, g_part1[((size_t)(b * XT + x)) * NN + j]);
        val = m;
    }

    red[tid] = val;
    __syncthreads();
#pragma unroll
    for (int s = TPB_RED / 2; s > 0; s >>= 1) {
        if (tid < s) red[tid] += red[tid + s];
        __syncthreads();
    }
    if (tid == 0)
        atomicAdd(out, red[0] * (1.0f / ((float)BB * (float)NN)));
}

extern "C" void kernel_launch(void* const* d_in, const int* in_sizes, int n_in,
                              void* d_out, int out_size) {
    const float* pred = (const float*)d_in[0];
    const float* gt   = (const float*)d_in[1];
    float*       out  = (float*)d_out;

    dim3 grid(XT, GSPLIT, BB);   // 8 x 32 x 4 = 1024 blocks, single launch
    chamfer_fused_kernel<<<grid, TPB>>>(pred, gt, out);

    chamfer_reduce_kernel<<<(2 * BB * NN) / TPB_RED, TPB_RED>>>(pred, out);
}